// round 11
// baseline (speedup 1.0000x reference)
#include <cuda_runtime.h>
#include <math.h>

// Problem constants (fixed shapes; derived defensively at launch)
#define LMAX 50
#define MMAX 50
#define PI_F  3.14159265358979323846f
#define TWO_PI_F 6.28318530717958647692f
#define NP 2048          // max point count per batch
#define NB 256           // y-buckets for counting sort

// ---------------- device scratch (no allocations allowed) ----------------
__device__ float4 g_pts[4 * NP];            // bucket-sorted (y, x=phi, rho, _)
__device__ int    g_off[4 * (NB + 1)];      // bucket offsets per batch
__device__ float  g_interp[4 * 131072];     // (B, NLAT*NLON)
__device__ float  g_ctabT[MMAX * 1024];     // [m][j] cos(2*pi*m*j/NLON)
__device__ float  g_xfT[4 * MMAX * 512];    // [b][m][k]

__device__ __forceinline__ int ybucket(float y) {
    // y + pi in [0, pi] -> [0, NB]; monotone in y, clamped
    int bk = (int)((y + PI_F) * ((float)NB / PI_F));
    return min(max(bk, 0), NB - 1);
}

// ---------------- zero the scalar output ----------------
__global__ void zero_kernel(float* out) { out[0] = 0.0f; }

// ---------------- cosine table (transposed): ctabT[m][j] = cos(2*pi*m*j/NLON) ----------------
__global__ void ctabT_kernel(int NLON) {
    int i = blockIdx.x * blockDim.x + threadIdx.x;
    if (i >= NLON * MMAX) return;
    int m = i / NLON;
    int j = i % NLON;
    g_ctabT[m * NLON + j] = cospif((float)(2 * m * j) / (float)NLON);
}

// ---------------- stage 1: cart->sph + counting sort into y-buckets ----------------
__global__ __launch_bounds__(512) void prep_bucket_kernel(
    const float* __restrict__ pred, int N) {
    __shared__ float sy[NP], sx[NP], sr[NP];
    __shared__ int cnt[NB + 1];
    __shared__ int off[NB + 1];
    int b = blockIdx.x;
    int tid = threadIdx.x;
    if (tid <= NB) cnt[tid] = 0;
    __syncthreads();
    for (int i = tid; i < N; i += 512) {
        float x = pred[3 * (b * N + i) + 0];
        float y = pred[3 * (b * N + i) + 1];
        float z = pred[3 * (b * N + i) + 2];
        float rho = sqrtf(x * x + y * y + z * z);
        float yy = acosf(z / rho) - PI_F;
        sy[i] = yy;
        sx[i] = atan2f(y, x);
        sr[i] = rho;
        atomicAdd(&cnt[ybucket(yy)], 1);
    }
    __syncthreads();
    if (tid == 0) {
        int acc = 0;
        for (int i2 = 0; i2 < NB; ++i2) { off[i2] = acc; acc += cnt[i2]; }
        off[NB] = acc;
    }
    __syncthreads();
    if (tid <= NB) {
        g_off[b * (NB + 1) + tid] = off[tid];
        cnt[tid] = 0;               // reuse as per-bucket cursor
    }
    __syncthreads();
    for (int i = tid; i < N; i += 512) {
        int bk = ybucket(sy[i]);
        int pos = off[bk] + atomicAdd(&cnt[bk], 1);
        g_pts[b * NP + pos] = make_float4(sy[i], sx[i], sr[i], 0.0f);
    }
}

// ---------------- stage 2: exact 3-NN via bucketed range scan ----------------
// Thread owns one phi-column (g1) and KG=4 theta-rows (different g0, same g1).
// Phase A: scan an expanded bucket window around bucket(g1) -> finite upper
//          bound bw on max-over-rows 3rd-NN distance (top-3 of a subset
//          upper-bounds the final d3 -> sound pruning).
// Phase B: counted scans over buckets covering |y-g1| <= sqrt(bw)*(1+eps),
//          window excluded. Insert comparisons use exact rn arithmetic
//          identical to the reference (round(dx^2)+round(dy^2)), so the
//          result equals full brute force (no ties in random float data).
#define KG 4
#define KNT 128

__global__ __launch_bounds__(KNT) void knn3_kernel(
    const float* __restrict__ grid, int M, int NLON, int NROW, int N) {
    __shared__ float4 pts[NP];
    __shared__ int off[NB + 1];
    int b  = blockIdx.z;
    int rg = blockIdx.y;                      // row group 0..NROW/KG-1
    int c  = blockIdx.x * KNT + threadIdx.x;  // column index
    for (int i = threadIdx.x; i < N; i += KNT) pts[i] = g_pts[b * NP + i];
    for (int i = threadIdx.x; i <= NB; i += KNT) off[i] = g_off[b * (NB + 1) + i];
    __syncthreads();

    int rowspan = NROW / KG;
    int m0 = rg * NLON + c;
    float g1 = grid[2 * m0 + 1];
    float g0k[KG];
#pragma unroll
    for (int k = 0; k < KG; ++k)
        g0k[k] = grid[2 * (m0 + k * rowspan * NLON)];

    float bd0[KG], bd1[KG], bd2[KG];
    float br0[KG], br1[KG], br2[KG];
#pragma unroll
    for (int k = 0; k < KG; ++k) {
        bd0[k] = bd1[k] = bd2[k] = 3.4e38f;
        br0[k] = br1[k] = br2[k] = 0.0f;
    }

    // Phase A: adaptive bucket window (no pruning, exact inserts)
    int bc = ybucket(g1);
    int b1 = bc, b2 = bc;
    while ((off[b2 + 1] - off[b1]) < 8 && (b1 > 0 || b2 < NB - 1)) {
        if (b1 > 0) --b1;
        if (b2 < NB - 1) ++b2;
    }
    int w0 = off[b1], w1 = off[b2 + 1];
    for (int j = w0; j < w1; ++j) {
        float4 p = pts[j];
        float t = g1 - p.x;
        float dyy = __fmul_rn(t, t);
        float rj = p.z;
#pragma unroll
        for (int k = 0; k < KG; ++k) {
            float dx = p.y - g0k[k];
            float d  = __fadd_rn(__fmul_rn(dx, dx), dyy);
            if (d < bd2[k]) {
                if (d < bd1[k]) {
                    bd2[k] = bd1[k]; br2[k] = br1[k];
                    if (d < bd0[k]) {
                        bd1[k] = bd0[k]; br1[k] = br0[k];
                        bd0[k] = d;      br0[k] = rj;
                    } else { bd1[k] = d; br1[k] = rj; }
                } else { bd2[k] = d; br2[k] = rj; }
            }
        }
    }
    float bw = fmaxf(fmaxf(bd2[0], bd2[1]), fmaxf(bd2[2], bd2[3]));

    // Phase B: counted scans over the covering bucket range, window excluded
    float s = sqrtf(bw);
    s = __fmaf_rn(s, 1e-6f, s);          // conservative margin
    int blo = ybucket(g1 - s);
    int bhi = ybucket(g1 + s);
    int jlo = off[blo], jhi = off[bhi + 1];
    int end1 = min(w0, jhi);
    int beg2 = max(w1, jlo);

    for (int seg = 0; seg < 2; ++seg) {
        int js = seg ? beg2 : jlo;
        int je = seg ? jhi  : end1;
        for (int j = js; j < je; ++j) {
            float4 p = pts[j];
            float t = g1 - p.x;
            float dyy = __fmul_rn(t, t);
            if (dyy < bw) {
                float rj = p.z;
#pragma unroll
                for (int k = 0; k < KG; ++k) {
                    float dx = p.y - g0k[k];
                    float d  = __fadd_rn(__fmul_rn(dx, dx), dyy);
                    if (d < bd2[k]) {
                        if (d < bd1[k]) {
                            bd2[k] = bd1[k]; br2[k] = br1[k];
                            if (d < bd0[k]) {
                                bd1[k] = bd0[k]; br1[k] = br0[k];
                                bd0[k] = d;      br0[k] = rj;
                            } else { bd1[k] = d; br1[k] = rj; }
                        } else { bd2[k] = d; br2[k] = rj; }
                        bw = fmaxf(fmaxf(bd2[0], bd2[1]), fmaxf(bd2[2], bd2[3]));
                    }
                }
            }
        }
    }

#pragma unroll
    for (int k = 0; k < KG; ++k) {
        float s0 = sqrtf(bd0[k]);
        float s1 = sqrtf(bd1[k]);
        float s2 = sqrtf(bd2[k]);
        // weights PROPORTIONAL to distance (as in reference source)
        float v = (s0 * br0[k] + s1 * br1[k] + s2 * br2[k]) / (s0 + s1 + s2);
        g_interp[b * M + m0 + k * rowspan * NLON] = v;
    }
}

// ---------------- stage 3: warp-per-(row,m) dot products ----------------
__global__ __launch_bounds__(256) void xf3_kernel(int NLAT, int NLON) {
    __shared__ float srow[1024];
    int bk = blockIdx.x;
    int b = bk / NLAT;
    int k = bk % NLAT;
    for (int j = threadIdx.x; j < NLON; j += 256)
        srow[j] = g_interp[bk * NLON + j];
    __syncthreads();
    int w    = threadIdx.x >> 5;
    int lane = threadIdx.x & 31;
    float inv = 1.0f / (float)NLON;
    for (int m = w; m < MMAX; m += 8) {
        const float* ct = g_ctabT + m * NLON;
        float acc = 0.0f;
        for (int j = lane; j < NLON; j += 32)
            acc = fmaf(srow[j], ct[j], acc);
#pragma unroll
        for (int o = 16; o > 0; o >>= 1)
            acc += __shfl_down_sync(0xffffffffu, acc, o);
        if (lane == 0)
            g_xfT[(b * MMAX + m) * NLAT + k] = acc * inv;
    }
}

// ---------------- stage 4+5 fused: coeff + weighted MSE ----------------
__global__ __launch_bounds__(256) void coeff_loss_kernel(
    const float* __restrict__ pct, const float* __restrict__ target,
    const float* __restrict__ rect, float* __restrict__ out,
    int B, int NLAT) {
    __shared__ float sm[8];
    if (threadIdx.x < 8) sm[threadIdx.x] = 0.0f;
    __syncthreads();
    int w    = blockIdx.x * 8 + (threadIdx.x >> 5);
    int lane = threadIdx.x & 31;
    if (w < B * LMAX * MMAX) {
        int b = w / (LMAX * MMAX);
        int r = w % (LMAX * MMAX);
        int l = r / MMAX;
        int m = r % MMAX;
        const float* xp = g_xfT + (b * MMAX + m) * NLAT;
        const float* pp = pct + (m * LMAX + l) * NLAT;
        float acc = 0.0f;
        for (int k = lane; k < NLAT; k += 32)
            acc = fmaf(xp[k], pp[k], acc);
#pragma unroll
        for (int o = 16; o > 0; o >>= 1)
            acc += __shfl_down_sync(0xffffffffu, acc, o);
        if (lane == 0) {
            float cf = acc * TWO_PI_F;
            float d = cf - target[w];
            sm[threadIdx.x >> 5] = d * d * rect[l] / (float)B;
        }
    }
    __syncthreads();
    if (threadIdx.x == 0) {
        float s = (sm[0] + sm[1]) + (sm[2] + sm[3])
                + (sm[4] + sm[5]) + (sm[6] + sm[7]);
        atomicAdd(out, s);
    }
}

// ---------------- launch ----------------
extern "C" void kernel_launch(void* const* d_in, const int* in_sizes, int n_in,
                              void* d_out, int out_size) {
    const float* pred   = (const float*)d_in[0];
    const float* target = (const float*)d_in[1];
    const float* grid   = (const float*)d_in[2];
    const float* pct    = (const float*)d_in[3];
    const float* rect   = (const float*)d_in[4];

    int B    = in_sizes[1] / (LMAX * MMAX);      // 2
    int N    = in_sizes[0] / (3 * B);            // 2048
    int M    = in_sizes[2] / 2;                  // 131072
    int NLAT = in_sizes[3] / (LMAX * MMAX);      // 256
    int NLON = M / NLAT;                         // 512

    zero_kernel<<<1, 1>>>((float*)d_out);
    ctabT_kernel<<<(NLON * MMAX + 255) / 256, 256>>>(NLON);
    prep_bucket_kernel<<<B, 512>>>(pred, N);

    dim3 kgrid(NLON / KNT, NLAT / KG, B);        // 4 x 64 x 2 = 512 CTAs
    knn3_kernel<<<kgrid, KNT>>>(grid, M, NLON, NLAT, N);

    xf3_kernel<<<B * NLAT, 256>>>(NLAT, NLON);

    int nout = B * LMAX * MMAX;
    coeff_loss_kernel<<<(nout + 7) / 8, 256>>>(pct, target, rect,
                                               (float*)d_out, B, NLAT);
}

// round 12
// speedup vs baseline: 4.2045x; 4.2045x over previous
#include <cuda_runtime.h>
#include <math.h>

// Problem constants (fixed shapes; derived defensively at launch)
#define LMAX 50
#define MMAX 50
#define PI_F  3.14159265358979323846f
#define TWO_PI_F 6.28318530717958647692f
#define NP 2048          // max point count per batch
#define NB 256           // y-buckets for counting sort
#define BH (PI_F / (float)NB)   // bucket height in y

// ---------------- device scratch (no allocations allowed) ----------------
__device__ float4 g_pts[4 * NP];            // bucket-sorted (y, x=phi, rho, _)
__device__ int    g_off[4 * (NB + 1)];      // bucket offsets per batch
__device__ float  g_interp[4 * 131072];     // (B, NLAT*NLON)
__device__ float  g_ctabT[MMAX * 1024];     // [m][j] cos(2*pi*m*j/NLON)
__device__ float  g_xfT[4 * MMAX * 512];    // [b][m][k]

__device__ __forceinline__ int ybucket(float y) {
    // y + pi in [0, pi] -> [0, NB]; monotone in y, clamped
    int bk = (int)((y + PI_F) * ((float)NB / PI_F));
    return min(max(bk, 0), NB - 1);
}

// ---------------- zero the scalar output ----------------
__global__ void zero_kernel(float* out) { out[0] = 0.0f; }

// ---------------- cosine table (transposed): ctabT[m][j] = cos(2*pi*m*j/NLON) ----------------
__global__ void ctabT_kernel(int NLON) {
    int i = blockIdx.x * blockDim.x + threadIdx.x;
    if (i >= NLON * MMAX) return;
    int m = i / NLON;
    int j = i % NLON;
    g_ctabT[m * NLON + j] = cospif((float)(2 * m * j) / (float)NLON);
}

// ---------------- stage 1: cart->sph + counting sort into y-buckets ----------------
__global__ __launch_bounds__(512) void prep_bucket_kernel(
    const float* __restrict__ pred, int N) {
    __shared__ float sy[NP], sx[NP], sr[NP];
    __shared__ int cnt[NB + 1];
    __shared__ int off[NB + 1];
    int b = blockIdx.x;
    int tid = threadIdx.x;
    if (tid <= NB) cnt[tid] = 0;
    __syncthreads();
    for (int i = tid; i < N; i += 512) {
        float x = pred[3 * (b * N + i) + 0];
        float y = pred[3 * (b * N + i) + 1];
        float z = pred[3 * (b * N + i) + 2];
        float rho = sqrtf(x * x + y * y + z * z);
        float yy = acosf(z / rho) - PI_F;
        sy[i] = yy;
        sx[i] = atan2f(y, x);
        sr[i] = rho;
        atomicAdd(&cnt[ybucket(yy)], 1);
    }
    __syncthreads();
    if (tid == 0) {
        int acc = 0;
        for (int i2 = 0; i2 < NB; ++i2) { off[i2] = acc; acc += cnt[i2]; }
        off[NB] = acc;
    }
    __syncthreads();
    if (tid <= NB) {
        g_off[b * (NB + 1) + tid] = off[tid];
        cnt[tid] = 0;               // reuse as per-bucket cursor
    }
    __syncthreads();
    for (int i = tid; i < N; i += 512) {
        int bk = ybucket(sy[i]);
        int pos = off[bk] + atomicAdd(&cnt[bk], 1);
        g_pts[b * NP + pos] = make_float4(sy[i], sx[i], sr[i], 0.0f);
    }
}

// ---------------- stage 2: exact 3-NN via outward bucket walk ----------------
// Thread owns one longitude column (g1) and 2 ADJACENT latitude rows (g0
// spacing pi/256 -> tight shared bound). Buckets are walked outward from
// bucket(g1), always taking the side whose bucket edge is nearer; the edge
// distance (with 0.999/-1e-6 slack dominating bucketization rounding) lower-
// bounds dy for every point in that bucket, so exiting when min-edge^2 >= bw
// is provably exact. Candidate arithmetic is bit-identical to the reference
// (round(dx^2)+round(dy^2)) so results equal full brute force.
#define KG2 2
#define KNT4 128

__global__ __launch_bounds__(KNT4) void knn4_kernel(
    const float* __restrict__ grid, int M, int NLON, int NROW, int N) {
    __shared__ float4 pts[NP];
    __shared__ int off[NB + 1];
    int b  = blockIdx.z;
    int rg = blockIdx.y;                       // adjacent row-pair index
    int c  = blockIdx.x * KNT4 + threadIdx.x;  // column index
    for (int i = threadIdx.x; i < N; i += KNT4) pts[i] = g_pts[b * NP + i];
    for (int i = threadIdx.x; i <= NB; i += KNT4) off[i] = g_off[b * (NB + 1) + i];
    __syncthreads();

    int m0 = (rg * KG2) * NLON + c;
    float g1 = grid[2 * m0 + 1];
    float g0k[KG2];
    g0k[0] = grid[2 * m0];
    g0k[1] = grid[2 * (m0 + NLON)];

    float bd0[KG2], bd1[KG2], bd2[KG2];
    float br0[KG2], br1[KG2], br2[KG2];
#pragma unroll
    for (int k = 0; k < KG2; ++k) {
        bd0[k] = bd1[k] = bd2[k] = 3.4e38f;
        br0[k] = br1[k] = br2[k] = 0.0f;
    }
    float bw = 3.4e38f;   // max over rows of current 3rd-best d^2

    int bc = ybucket(g1);
    int lo = bc, hi = bc + 1;  // next bucket to process on each side

    while (true) {
        // lower bound on dy for every point in the next bucket of each side
        float bl = 1e30f, bh = 1e30f;
        if (lo >= 0) {
            float e = fmaf((float)(lo + 1), BH, -PI_F);   // top edge of bucket lo
            bl = fmaxf((g1 - e) * 0.999f - 1e-6f, 0.0f);
        }
        if (hi < NB) {
            float e = fmaf((float)hi, BH, -PI_F);         // bottom edge of bucket hi
            bh = fmaxf((e - g1) * 0.999f - 1e-6f, 0.0f);
        }
        bool tl = bl <= bh;
        float bmin = tl ? bl : bh;
        if (__fmul_rn(bmin, bmin) >= bw) break;   // exact exit / both exhausted
        int bk;
        if (tl) { bk = lo; --lo; } else { bk = hi; ++hi; }
        int o1 = off[bk + 1];
        for (int j = off[bk]; j < o1; ++j) {
            float4 p = pts[j];
            float t = g1 - p.x;
            float dyy = __fmul_rn(t, t);
            if (dyy < bw) {
                float rj = p.z;
#pragma unroll
                for (int k = 0; k < KG2; ++k) {
                    float dx = p.y - g0k[k];
                    float d  = __fadd_rn(__fmul_rn(dx, dx), dyy);
                    if (d < bd2[k]) {
                        if (d < bd1[k]) {
                            bd2[k] = bd1[k]; br2[k] = br1[k];
                            if (d < bd0[k]) {
                                bd1[k] = bd0[k]; br1[k] = br0[k];
                                bd0[k] = d;      br0[k] = rj;
                            } else { bd1[k] = d; br1[k] = rj; }
                        } else { bd2[k] = d; br2[k] = rj; }
                        bw = fmaxf(bd2[0], bd2[1]);
                    }
                }
            }
        }
    }

#pragma unroll
    for (int k = 0; k < KG2; ++k) {
        float s0 = sqrtf(bd0[k]);
        float s1 = sqrtf(bd1[k]);
        float s2 = sqrtf(bd2[k]);
        // weights PROPORTIONAL to distance (as in reference source)
        float v = (s0 * br0[k] + s1 * br1[k] + s2 * br2[k]) / (s0 + s1 + s2);
        g_interp[b * M + m0 + k * NLON] = v;
    }
}

// ---------------- stage 3: warp-per-(row,m) dot products ----------------
__global__ __launch_bounds__(256) void xf3_kernel(int NLAT, int NLON) {
    __shared__ float srow[1024];
    int bk = blockIdx.x;
    int b = bk / NLAT;
    int k = bk % NLAT;
    for (int j = threadIdx.x; j < NLON; j += 256)
        srow[j] = g_interp[bk * NLON + j];
    __syncthreads();
    int w    = threadIdx.x >> 5;
    int lane = threadIdx.x & 31;
    float inv = 1.0f / (float)NLON;
    for (int m = w; m < MMAX; m += 8) {
        const float* ct = g_ctabT + m * NLON;
        float acc = 0.0f;
        for (int j = lane; j < NLON; j += 32)
            acc = fmaf(srow[j], ct[j], acc);
#pragma unroll
        for (int o = 16; o > 0; o >>= 1)
            acc += __shfl_down_sync(0xffffffffu, acc, o);
        if (lane == 0)
            g_xfT[(b * MMAX + m) * NLAT + k] = acc * inv;
    }
}

// ---------------- stage 4+5 fused: coeff + weighted MSE ----------------
__global__ __launch_bounds__(256) void coeff_loss_kernel(
    const float* __restrict__ pct, const float* __restrict__ target,
    const float* __restrict__ rect, float* __restrict__ out,
    int B, int NLAT) {
    __shared__ float sm[8];
    if (threadIdx.x < 8) sm[threadIdx.x] = 0.0f;
    __syncthreads();
    int w    = blockIdx.x * 8 + (threadIdx.x >> 5);
    int lane = threadIdx.x & 31;
    if (w < B * LMAX * MMAX) {
        int b = w / (LMAX * MMAX);
        int r = w % (LMAX * MMAX);
        int l = r / MMAX;
        int m = r % MMAX;
        const float* xp = g_xfT + (b * MMAX + m) * NLAT;
        const float* pp = pct + (m * LMAX + l) * NLAT;
        float acc = 0.0f;
        for (int k = lane; k < NLAT; k += 32)
            acc = fmaf(xp[k], pp[k], acc);
#pragma unroll
        for (int o = 16; o > 0; o >>= 1)
            acc += __shfl_down_sync(0xffffffffu, acc, o);
        if (lane == 0) {
            float cf = acc * TWO_PI_F;
            float d = cf - target[w];
            sm[threadIdx.x >> 5] = d * d * rect[l] / (float)B;
        }
    }
    __syncthreads();
    if (threadIdx.x == 0) {
        float s = (sm[0] + sm[1]) + (sm[2] + sm[3])
                + (sm[4] + sm[5]) + (sm[6] + sm[7]);
        atomicAdd(out, s);
    }
}

// ---------------- launch ----------------
extern "C" void kernel_launch(void* const* d_in, const int* in_sizes, int n_in,
                              void* d_out, int out_size) {
    const float* pred   = (const float*)d_in[0];
    const float* target = (const float*)d_in[1];
    const float* grid   = (const float*)d_in[2];
    const float* pct    = (const float*)d_in[3];
    const float* rect   = (const float*)d_in[4];

    int B    = in_sizes[1] / (LMAX * MMAX);      // 2
    int N    = in_sizes[0] / (3 * B);            // 2048
    int M    = in_sizes[2] / 2;                  // 131072
    int NLAT = in_sizes[3] / (LMAX * MMAX);      // 256
    int NLON = M / NLAT;                         // 512

    zero_kernel<<<1, 1>>>((float*)d_out);
    ctabT_kernel<<<(NLON * MMAX + 255) / 256, 256>>>(NLON);
    prep_bucket_kernel<<<B, 512>>>(pred, N);

    dim3 kgrid(NLON / KNT4, NLAT / KG2, B);      // 4 x 128 x 2 = 1024 CTAs
    knn4_kernel<<<kgrid, KNT4>>>(grid, M, NLON, NLAT, N);

    xf3_kernel<<<B * NLAT, 256>>>(NLAT, NLON);

    int nout = B * LMAX * MMAX;
    coeff_loss_kernel<<<(nout + 7) / 8, 256>>>(pct, target, rect,
                                               (float*)d_out, B, NLAT);
}

// round 13
// speedup vs baseline: 6.0377x; 1.4360x over previous
#include <cuda_runtime.h>
#include <math.h>

// Problem constants (fixed shapes; derived defensively at launch)
#define LMAX 50
#define MMAX 50
#define PI_F  3.14159265358979323846f
#define TWO_PI_F 6.28318530717958647692f
#define NP 2048          // max point count per batch
#define NB 256           // y-buckets for counting sort
#define BH (PI_F / (float)NB)   // bucket height in y

// ---------------- device scratch (no allocations allowed) ----------------
__device__ float4 g_pts[4 * NP];            // bucket-sorted (y, x=phi, rho, _)
__device__ int    g_off[4 * (NB + 1)];      // bucket offsets per batch
__device__ float  g_interp[4 * 131072];     // (B, NLAT*NLON)
__device__ float  g_ctabT[MMAX * 1024];     // [m][j] cos(2*pi*m*j/NLON)
__device__ float  g_xfT[4 * MMAX * 512];    // [b][m][k]

__device__ __forceinline__ int ybucket(float y) {
    // y + pi in [0, pi] -> [0, NB]; monotone in y, clamped
    int bk = (int)((y + PI_F) * ((float)NB / PI_F));
    return min(max(bk, 0), NB - 1);
}

// ---------------- zero the scalar output ----------------
__global__ void zero_kernel(float* out) { out[0] = 0.0f; }

// ---------------- cosine table (transposed): ctabT[m][j] = cos(2*pi*m*j/NLON) ----------------
__global__ void ctabT_kernel(int NLON) {
    int i = blockIdx.x * blockDim.x + threadIdx.x;
    if (i >= NLON * MMAX) return;
    int m = i / NLON;
    int j = i % NLON;
    g_ctabT[m * NLON + j] = cospif((float)(2 * m * j) / (float)NLON);
}

// ---------------- stage 1: cart->sph + counting sort into y-buckets ----------------
__global__ __launch_bounds__(512) void prep_bucket_kernel(
    const float* __restrict__ pred, int N) {
    __shared__ float sy[NP], sx[NP], sr[NP];
    __shared__ int cnt[NB + 1];
    __shared__ int off[NB + 1];
    int b = blockIdx.x;
    int tid = threadIdx.x;
    if (tid <= NB) cnt[tid] = 0;
    __syncthreads();
    for (int i = tid; i < N; i += 512) {
        float x = pred[3 * (b * N + i) + 0];
        float y = pred[3 * (b * N + i) + 1];
        float z = pred[3 * (b * N + i) + 2];
        float rho = sqrtf(x * x + y * y + z * z);
        float yy = acosf(z / rho) - PI_F;
        sy[i] = yy;
        sx[i] = atan2f(y, x);
        sr[i] = rho;
        atomicAdd(&cnt[ybucket(yy)], 1);
    }
    __syncthreads();
    if (tid == 0) {
        int acc = 0;
        for (int i2 = 0; i2 < NB; ++i2) { off[i2] = acc; acc += cnt[i2]; }
        off[NB] = acc;
    }
    __syncthreads();
    if (tid <= NB) {
        g_off[b * (NB + 1) + tid] = off[tid];
        cnt[tid] = 0;               // reuse as per-bucket cursor
    }
    __syncthreads();
    for (int i = tid; i < N; i += 512) {
        int bk = ybucket(sy[i]);
        int pos = off[bk] + atomicAdd(&cnt[bk], 1);
        g_pts[b * NP + pos] = make_float4(sy[i], sx[i], sr[i], 0.0f);
    }
}

// ---------------- stage 2: exact 3-NN, warp-uniform bucket walk ----------------
// Each WARP owns one longitude column (g1 identical across lanes); each lane
// owns one latitude row (g0 per-lane). The outward bucket walk (side choice,
// lo/hi, candidate j sequence) depends only on warp-uniform values -> zero
// control divergence; lanes that satisfied their own exact exit bound simply
// predicate off. Bucket-edge lower bound with 0.999/-1e-6 slack dominates
// bucketization rounding (validated R12). Candidate arithmetic is bit-exact
// to the reference: round(dx^2) + round(dy^2).
#define KNT5 256

__global__ __launch_bounds__(KNT5) void knn5_kernel(
    const float* __restrict__ grid, int M, int NLON, int NROW, int N) {
    __shared__ float ys[NP], xs[NP], rs[NP];
    __shared__ int off[NB + 1];
    int b    = blockIdx.z;
    int rgrp = blockIdx.y;                 // 32-row group
    int cg   = blockIdx.x;                 // 8-column group
    int w    = threadIdx.x >> 5;
    int lane = threadIdx.x & 31;
    for (int i = threadIdx.x; i < N; i += KNT5) {
        float4 p = g_pts[b * NP + i];
        ys[i] = p.x; xs[i] = p.y; rs[i] = p.z;
    }
    for (int i = threadIdx.x; i <= NB; i += KNT5) off[i] = g_off[b * (NB + 1) + i];
    __syncthreads();

    int c = cg * 8 + w;                    // column: warp-uniform
    int r = rgrp * 32 + lane;              // row: per-lane
    int m = r * NLON + c;
    float g0 = grid[2 * m];                // row coordinate (per-lane)
    float g1 = grid[2 * m + 1];            // column coordinate (warp-uniform)

    float bd0 = 3.4e38f, bd1 = 3.4e38f, bd2 = 3.4e38f;
    float br0 = 0.0f, br1 = 0.0f, br2 = 0.0f;

    int bc = ybucket(g1);
    int lo = bc, hi = bc + 1;              // next bucket on each side

    while (true) {
        float bl = 1e30f, bh = 1e30f;
        if (lo >= 0) {
            float e = fmaf((float)(lo + 1), BH, -PI_F);   // top edge of bucket lo
            bl = fmaxf((g1 - e) * 0.999f - 1e-6f, 0.0f);
        }
        if (hi < NB) {
            float e = fmaf((float)hi, BH, -PI_F);         // bottom edge of bucket hi
            bh = fmaxf((e - g1) * 0.999f - 1e-6f, 0.0f);
        }
        bool tl = bl <= bh;                // warp-uniform choice
        float bmin = tl ? bl : bh;
        if (__fmul_rn(bmin, bmin) >= bd2) break;  // per-lane exact exit
        int bk;
        if (tl) { bk = lo; --lo; } else { bk = hi; ++hi; }
        int o1 = off[bk + 1];
        for (int j = off[bk]; j < o1; ++j) {      // warp-uniform j sequence
            float t = g1 - ys[j];                 // uniform
            float dyy = __fmul_rn(t, t);          // uniform
            if (dyy < bd2) {
                float dx = xs[j] - g0;            // per-lane
                float d  = __fadd_rn(__fmul_rn(dx, dx), dyy);
                if (d < bd2) {
                    float rj = rs[j];
                    if (d < bd1) {
                        bd2 = bd1; br2 = br1;
                        if (d < bd0) { bd1 = bd0; br1 = br0; bd0 = d; br0 = rj; }
                        else         { bd1 = d;   br1 = rj; }
                    } else { bd2 = d; br2 = rj; }
                }
            }
        }
    }

    float s0 = sqrtf(bd0);
    float s1 = sqrtf(bd1);
    float s2 = sqrtf(bd2);
    // weights PROPORTIONAL to distance (as in reference source)
    float v = (s0 * br0 + s1 * br1 + s2 * br2) / (s0 + s1 + s2);
    g_interp[b * M + m] = v;
}

// ---------------- stage 3: warp-per-(row,m) dot products ----------------
__global__ __launch_bounds__(256) void xf3_kernel(int NLAT, int NLON) {
    __shared__ float srow[1024];
    int bk = blockIdx.x;
    int b = bk / NLAT;
    int k = bk % NLAT;
    for (int j = threadIdx.x; j < NLON; j += 256)
        srow[j] = g_interp[bk * NLON + j];
    __syncthreads();
    int w    = threadIdx.x >> 5;
    int lane = threadIdx.x & 31;
    float inv = 1.0f / (float)NLON;
    for (int m = w; m < MMAX; m += 8) {
        const float* ct = g_ctabT + m * NLON;
        float acc = 0.0f;
        for (int j = lane; j < NLON; j += 32)
            acc = fmaf(srow[j], ct[j], acc);
#pragma unroll
        for (int o = 16; o > 0; o >>= 1)
            acc += __shfl_down_sync(0xffffffffu, acc, o);
        if (lane == 0)
            g_xfT[(b * MMAX + m) * NLAT + k] = acc * inv;
    }
}

// ---------------- stage 4+5 fused: coeff + weighted MSE ----------------
__global__ __launch_bounds__(256) void coeff_loss_kernel(
    const float* __restrict__ pct, const float* __restrict__ target,
    const float* __restrict__ rect, float* __restrict__ out,
    int B, int NLAT) {
    __shared__ float sm[8];
    if (threadIdx.x < 8) sm[threadIdx.x] = 0.0f;
    __syncthreads();
    int w    = blockIdx.x * 8 + (threadIdx.x >> 5);
    int lane = threadIdx.x & 31;
    if (w < B * LMAX * MMAX) {
        int b = w / (LMAX * MMAX);
        int r = w % (LMAX * MMAX);
        int l = r / MMAX;
        int m = r % MMAX;
        const float* xp = g_xfT + (b * MMAX + m) * NLAT;
        const float* pp = pct + (m * LMAX + l) * NLAT;
        float acc = 0.0f;
        for (int k = lane; k < NLAT; k += 32)
            acc = fmaf(xp[k], pp[k], acc);
#pragma unroll
        for (int o = 16; o > 0; o >>= 1)
            acc += __shfl_down_sync(0xffffffffu, acc, o);
        if (lane == 0) {
            float cf = acc * TWO_PI_F;
            float d = cf - target[w];
            sm[threadIdx.x >> 5] = d * d * rect[l] / (float)B;
        }
    }
    __syncthreads();
    if (threadIdx.x == 0) {
        float s = (sm[0] + sm[1]) + (sm[2] + sm[3])
                + (sm[4] + sm[5]) + (sm[6] + sm[7]);
        atomicAdd(out, s);
    }
}

// ---------------- launch ----------------
extern "C" void kernel_launch(void* const* d_in, const int* in_sizes, int n_in,
                              void* d_out, int out_size) {
    const float* pred   = (const float*)d_in[0];
    const float* target = (const float*)d_in[1];
    const float* grid   = (const float*)d_in[2];
    const float* pct    = (const float*)d_in[3];
    const float* rect   = (const float*)d_in[4];

    int B    = in_sizes[1] / (LMAX * MMAX);      // 2
    int N    = in_sizes[0] / (3 * B);            // 2048
    int M    = in_sizes[2] / 2;                  // 131072
    int NLAT = in_sizes[3] / (LMAX * MMAX);      // 256
    int NLON = M / NLAT;                         // 512

    zero_kernel<<<1, 1>>>((float*)d_out);
    ctabT_kernel<<<(NLON * MMAX + 255) / 256, 256>>>(NLON);
    prep_bucket_kernel<<<B, 512>>>(pred, N);

    dim3 kgrid(NLON / 8, NLAT / 32, B);          // 64 x 8 x 2 = 1024 CTAs
    knn5_kernel<<<kgrid, KNT5>>>(grid, M, NLON, NLAT, N);

    xf3_kernel<<<B * NLAT, 256>>>(NLAT, NLON);

    int nout = B * LMAX * MMAX;
    coeff_loss_kernel<<<(nout + 7) / 8, 256>>>(pct, target, rect,
                                               (float*)d_out, B, NLAT);
}

// round 14
// speedup vs baseline: 7.0111x; 1.1612x over previous
#include <cuda_runtime.h>
#include <math.h>

// Problem constants (fixed shapes; derived defensively at launch)
#define LMAX 50
#define MMAX 50
#define PI_F  3.14159265358979323846f
#define TWO_PI_F 6.28318530717958647692f
#define NP 2048          // max point count per batch
#define NB 256           // y-buckets for counting sort
#define BH (PI_F / (float)NB)   // bucket height in y

// ---------------- device scratch (no allocations allowed) ----------------
__device__ float2 g_pxy[4 * NP];            // bucket-sorted (y, x=phi)
__device__ float  g_pr[4 * NP];             // matching rho
__device__ int    g_off[4 * (NB + 1)];      // bucket offsets per batch
__device__ float  g_interp[4 * 131072];     // (B, NLAT*NLON)
__device__ float  g_ctabT[MMAX * 1024];     // [m][j] cos(2*pi*m*j/NLON)
__device__ float  g_xfT[4 * MMAX * 512];    // [b][m][k]

__device__ __forceinline__ int ybucket(float y) {
    // y + pi in [0, pi] -> [0, NB]; monotone in y, clamped
    int bk = (int)((y + PI_F) * ((float)NB / PI_F));
    return min(max(bk, 0), NB - 1);
}

// ---------------- cosine table (transposed): ctabT[m][j] = cos(2*pi*m*j/NLON) ----------------
__global__ void ctabT_kernel(int NLON) {
    int i = blockIdx.x * blockDim.x + threadIdx.x;
    if (i >= NLON * MMAX) return;
    int m = i / NLON;
    int j = i % NLON;
    g_ctabT[m * NLON + j] = cospif((float)(2 * m * j) / (float)NLON);
}

// ---------------- stage 1: cart->sph + counting sort into y-buckets ----------------
// Also zeroes the scalar output (saves a launch).
__global__ __launch_bounds__(512) void prep_bucket_kernel(
    const float* __restrict__ pred, int N, float* __restrict__ out) {
    __shared__ float sy[NP], sx[NP], sr[NP];
    __shared__ int cnt[NB + 1];
    __shared__ int off[NB + 1];
    int b = blockIdx.x;
    int tid = threadIdx.x;
    if (b == 0 && tid == 0) out[0] = 0.0f;
    if (tid <= NB) cnt[tid] = 0;
    __syncthreads();
    for (int i = tid; i < N; i += 512) {
        float x = pred[3 * (b * N + i) + 0];
        float y = pred[3 * (b * N + i) + 1];
        float z = pred[3 * (b * N + i) + 2];
        float rho = sqrtf(x * x + y * y + z * z);
        float yy = acosf(z / rho) - PI_F;
        sy[i] = yy;
        sx[i] = atan2f(y, x);
        sr[i] = rho;
        atomicAdd(&cnt[ybucket(yy)], 1);
    }
    __syncthreads();
    if (tid == 0) {
        int acc = 0;
        for (int i2 = 0; i2 < NB; ++i2) { off[i2] = acc; acc += cnt[i2]; }
        off[NB] = acc;
    }
    __syncthreads();
    if (tid <= NB) {
        g_off[b * (NB + 1) + tid] = off[tid];
        cnt[tid] = 0;               // reuse as per-bucket cursor
    }
    __syncthreads();
    for (int i = tid; i < N; i += 512) {
        int bk = ybucket(sy[i]);
        int pos = off[bk] + atomicAdd(&cnt[bk], 1);
        g_pxy[b * NP + pos] = make_float2(sy[i], sx[i]);
        g_pr[b * NP + pos]  = sr[i];
    }
}

// ---------------- stage 2: exact 3-NN, warp-uniform bucket walk ----------------
// Each WARP owns one longitude column (g1 identical across lanes); each lane
// owns one latitude row (g0 per-lane). Walk/candidate sequence is warp-uniform
// -> zero control divergence. Bucket-edge lower bound with 0.999/-1e-6 slack
// dominates bucketization rounding (validated R12/R13). Candidate distance is
// bit-exact to the reference: round(dx^2) + round(dy^2); the removed dy-only
// pre-check was redundant (d >= dy^2, so d < bd2 implies it). Inner bucket
// scan unrolled x2 with sequential insert order preserved.
#define KNT6 256

#define KNN_INSERT(dv, jv)                                         \
    if ((dv) < bd2) {                                              \
        float rj = rsm[jv];                                        \
        if ((dv) < bd1) {                                          \
            bd2 = bd1; br2 = br1;                                  \
            if ((dv) < bd0) { bd1 = bd0; br1 = br0;                \
                              bd0 = (dv); br0 = rj; }              \
            else            { bd1 = (dv); br1 = rj; }              \
        } else { bd2 = (dv); br2 = rj; }                           \
    }

__global__ __launch_bounds__(KNT6) void knn6_kernel(
    const float* __restrict__ grid, int M, int NLON, int NROW, int N) {
    __shared__ float2 pxy[NP];
    __shared__ float  rsm[NP];
    __shared__ int off[NB + 1];
    int b    = blockIdx.z;
    int rgrp = blockIdx.y;                 // 32-row group
    int cg   = blockIdx.x;                 // 8-column group
    int w    = threadIdx.x >> 5;
    int lane = threadIdx.x & 31;
    for (int i = threadIdx.x; i < N; i += KNT6) {
        pxy[i] = g_pxy[b * NP + i];
        rsm[i] = g_pr[b * NP + i];
    }
    for (int i = threadIdx.x; i <= NB; i += KNT6) off[i] = g_off[b * (NB + 1) + i];
    __syncthreads();

    int c = cg * 8 + w;                    // column: warp-uniform
    int r = rgrp * 32 + lane;              // row: per-lane
    int m = r * NLON + c;
    float g0 = grid[2 * m];                // row coordinate (per-lane)
    float g1 = grid[2 * m + 1];            // column coordinate (warp-uniform)

    float bd0 = 3.4e38f, bd1 = 3.4e38f, bd2 = 3.4e38f;
    float br0 = 0.0f, br1 = 0.0f, br2 = 0.0f;

    int bc = ybucket(g1);
    int lo = bc, hi = bc + 1;              // next bucket on each side

    while (true) {
        float bl = 1e30f, bh = 1e30f;
        if (lo >= 0) {
            float e = fmaf((float)(lo + 1), BH, -PI_F);   // top edge of bucket lo
            bl = fmaxf((g1 - e) * 0.999f - 1e-6f, 0.0f);
        }
        if (hi < NB) {
            float e = fmaf((float)hi, BH, -PI_F);         // bottom edge of bucket hi
            bh = fmaxf((e - g1) * 0.999f - 1e-6f, 0.0f);
        }
        bool tl = bl <= bh;                // warp-uniform choice
        float bmin = tl ? bl : bh;
        if (__fmul_rn(bmin, bmin) >= bd2) break;  // per-lane exact exit
        int bk;
        if (tl) { bk = lo; --lo; } else { bk = hi; ++hi; }
        int j  = off[bk];
        int o1 = off[bk + 1];
        for (; j + 1 < o1; j += 2) {              // warp-uniform, unrolled x2
            float2 p0 = pxy[j];
            float2 p1 = pxy[j + 1];
            float t0  = g1 - p0.x;
            float dx0 = p0.y - g0;
            float d0  = __fadd_rn(__fmul_rn(dx0, dx0), __fmul_rn(t0, t0));
            float t1  = g1 - p1.x;
            float dx1 = p1.y - g0;
            float d1  = __fadd_rn(__fmul_rn(dx1, dx1), __fmul_rn(t1, t1));
            KNN_INSERT(d0, j);
            KNN_INSERT(d1, j + 1);
        }
        if (j < o1) {
            float2 p0 = pxy[j];
            float t0  = g1 - p0.x;
            float dx0 = p0.y - g0;
            float d0  = __fadd_rn(__fmul_rn(dx0, dx0), __fmul_rn(t0, t0));
            KNN_INSERT(d0, j);
        }
    }

    float s0 = sqrtf(bd0);
    float s1 = sqrtf(bd1);
    float s2 = sqrtf(bd2);
    // weights PROPORTIONAL to distance (as in reference source)
    float v = (s0 * br0 + s1 * br1 + s2 * br2) / (s0 + s1 + s2);
    g_interp[b * M + m] = v;
}

// ---------------- stage 3: warp-per-(row,m) dot products ----------------
__global__ __launch_bounds__(256) void xf3_kernel(int NLAT, int NLON) {
    __shared__ float srow[1024];
    int bk = blockIdx.x;
    int b = bk / NLAT;
    int k = bk % NLAT;
    for (int j = threadIdx.x; j < NLON; j += 256)
        srow[j] = g_interp[bk * NLON + j];
    __syncthreads();
    int w    = threadIdx.x >> 5;
    int lane = threadIdx.x & 31;
    float inv = 1.0f / (float)NLON;
    for (int m = w; m < MMAX; m += 8) {
        const float* ct = g_ctabT + m * NLON;
        float acc = 0.0f;
        for (int j = lane; j < NLON; j += 32)
            acc = fmaf(srow[j], ct[j], acc);
#pragma unroll
        for (int o = 16; o > 0; o >>= 1)
            acc += __shfl_down_sync(0xffffffffu, acc, o);
        if (lane == 0)
            g_xfT[(b * MMAX + m) * NLAT + k] = acc * inv;
    }
}

// ---------------- stage 4+5 fused: coeff + weighted MSE ----------------
__global__ __launch_bounds__(256) void coeff_loss_kernel(
    const float* __restrict__ pct, const float* __restrict__ target,
    const float* __restrict__ rect, float* __restrict__ out,
    int B, int NLAT) {
    __shared__ float sm[8];
    if (threadIdx.x < 8) sm[threadIdx.x] = 0.0f;
    __syncthreads();
    int w    = blockIdx.x * 8 + (threadIdx.x >> 5);
    int lane = threadIdx.x & 31;
    if (w < B * LMAX * MMAX) {
        int b = w / (LMAX * MMAX);
        int r = w % (LMAX * MMAX);
        int l = r / MMAX;
        int m = r % MMAX;
        const float* xp = g_xfT + (b * MMAX + m) * NLAT;
        const float* pp = pct + (m * LMAX + l) * NLAT;
        float acc = 0.0f;
        for (int k = lane; k < NLAT; k += 32)
            acc = fmaf(xp[k], pp[k], acc);
#pragma unroll
        for (int o = 16; o > 0; o >>= 1)
            acc += __shfl_down_sync(0xffffffffu, acc, o);
        if (lane == 0) {
            float cf = acc * TWO_PI_F;
            float d = cf - target[w];
            sm[threadIdx.x >> 5] = d * d * rect[l] / (float)B;
        }
    }
    __syncthreads();
    if (threadIdx.x == 0) {
        float s = (sm[0] + sm[1]) + (sm[2] + sm[3])
                + (sm[4] + sm[5]) + (sm[6] + sm[7]);
        atomicAdd(out, s);
    }
}

// ---------------- launch ----------------
extern "C" void kernel_launch(void* const* d_in, const int* in_sizes, int n_in,
                              void* d_out, int out_size) {
    const float* pred   = (const float*)d_in[0];
    const float* target = (const float*)d_in[1];
    const float* grid   = (const float*)d_in[2];
    const float* pct    = (const float*)d_in[3];
    const float* rect   = (const float*)d_in[4];

    int B    = in_sizes[1] / (LMAX * MMAX);      // 2
    int N    = in_sizes[0] / (3 * B);            // 2048
    int M    = in_sizes[2] / 2;                  // 131072
    int NLAT = in_sizes[3] / (LMAX * MMAX);      // 256
    int NLON = M / NLAT;                         // 512

    ctabT_kernel<<<(NLON * MMAX + 255) / 256, 256>>>(NLON);
    prep_bucket_kernel<<<B, 512>>>(pred, N, (float*)d_out);

    dim3 kgrid(NLON / 8, NLAT / 32, B);          // 64 x 8 x 2 = 1024 CTAs
    knn6_kernel<<<kgrid, KNT6>>>(grid, M, NLON, NLAT, N);

    xf3_kernel<<<B * NLAT, 256>>>(NLAT, NLON);

    int nout = B * LMAX * MMAX;
    coeff_loss_kernel<<<(nout + 7) / 8, 256>>>(pct, target, rect,
                                               (float*)d_out, B, NLAT);
}